// round 1
// baseline (speedup 1.0000x reference)
#include <cuda_runtime.h>
#include <cuda_bf16.h>
#include <cstdint>

#define N_NODES 50000
#define N_EDGES 850000
#define IN_F 512
#define HID_F 256
#define OUT_F 128

// ---------------- device scratch (no allocations allowed) ----------------
__device__ float g_hw1[N_NODES * HID_F];   // x @ W1
__device__ float g_h[N_NODES * HID_F];     // relu(layer1 out)
__device__ float g_hw2[N_NODES * OUT_F];   // h @ W2
__device__ float g_invdeg[N_NODES];
__device__ int   g_deg[N_NODES];
__device__ int   g_rowptr[N_NODES + 1];
__device__ int   g_pos[N_NODES];
__device__ int   g_esrc[N_EDGES];
__device__ float g_ew[N_EDGES];

// ---------------- CSR build ----------------
__global__ void init_kernel() {
    int i = blockIdx.x * blockDim.x + threadIdx.x;
    if (i < N_NODES) { g_deg[i] = 0; g_pos[i] = 0; }
}

__global__ void count_deg_kernel(const int* __restrict__ edst) {
    int e = blockIdx.x * blockDim.x + threadIdx.x;
    if (e < N_EDGES) atomicAdd(&g_deg[edst[e]], 1);
}

// single block, 1024 threads: exclusive scan of degrees -> rowptr, plus inv_deg
__global__ void scan_kernel() {
    __shared__ int partial[1024];
    const int tid = threadIdx.x;
    const int CH = (N_NODES + 1023) / 1024;  // 49
    int start = tid * CH;
    int stop = start + CH;
    if (stop > N_NODES) stop = N_NODES;

    int s = 0;
    for (int i = start; i < stop; ++i) s += g_deg[i];
    partial[tid] = s;
    __syncthreads();
    // inclusive scan
    for (int off = 1; off < 1024; off <<= 1) {
        int v = 0;
        if (tid >= off) v = partial[tid - off];
        __syncthreads();
        partial[tid] += v;
        __syncthreads();
    }
    int base = partial[tid] - s;  // exclusive prefix for this chunk
    for (int i = start; i < stop; ++i) {
        int d = g_deg[i];
        g_rowptr[i] = base;
        base += d;
        g_invdeg[i] = 1.0f / (float)(d > 0 ? d : 1);
    }
    if (tid == 0) g_rowptr[N_NODES] = partial[1023];
}

__global__ void build_csr_kernel(const int* __restrict__ esrc,
                                 const int* __restrict__ edst,
                                 const float* __restrict__ ew) {
    int e = blockIdx.x * blockDim.x + threadIdx.x;
    if (e >= N_EDGES) return;
    int dst = edst[e];
    int p = g_rowptr[dst] + atomicAdd(&g_pos[dst], 1);
    g_esrc[p] = esrc[e];
    g_ew[p] = ew[e];
}

// ---------------- tf32 MMA GEMM with 3-term split (fp32-accurate) ----------------
__device__ __forceinline__ void split_tf32(float f, uint32_t& hi, uint32_t& lo) {
    uint32_t h;
    asm("cvt.rna.tf32.f32 %0, %1;" : "=r"(h) : "f"(f));
    float r = f - __uint_as_float(h);
    uint32_t l;
    asm("cvt.rna.tf32.f32 %0, %1;" : "=r"(l) : "f"(r));
    hi = h; lo = l;
}

__device__ __forceinline__ void mma_tf32(float* c, const uint32_t* a, const uint32_t* b) {
    asm volatile(
        "mma.sync.aligned.m16n8k8.row.col.f32.tf32.tf32.f32 "
        "{%0,%1,%2,%3}, {%4,%5,%6,%7}, {%8,%9}, {%0,%1,%2,%3};\n"
        : "+f"(c[0]), "+f"(c[1]), "+f"(c[2]), "+f"(c[3])
        : "r"(a[0]), "r"(a[1]), "r"(a[2]), "r"(a[3]), "r"(b[0]), "r"(b[1]));
}

#define BM 128
#define BN 128
#define BK 32

// C[M,N] = A[M,K] @ B[K,N], all row-major fp32. N % 128 == 0, K % 32 == 0.
__global__ __launch_bounds__(256, 1)
void gemm_tf32_kernel(const float* __restrict__ A, const float* __restrict__ B,
                      float* __restrict__ C, int M, int K, int N) {
    __shared__ float As[BM][BK + 4];   // stride 36 floats (16B-aligned rows)
    __shared__ float Bs[BK][BN + 8];   // stride 136 floats (conflict-free frag loads)

    const int tid = threadIdx.x;
    const int wid = tid >> 5;
    const int lane = tid & 31;
    const int gid = lane >> 2;   // 0..7
    const int tig = lane & 3;    // 0..3
    const int warp_m = wid >> 1;             // 0..3
    const int warp_n = wid & 1;              // 0..1
    const int m_base = warp_m * 32;
    const int n_base = warp_n * 64;
    const int blockRow = blockIdx.y * BM;
    const int blockCol = blockIdx.x * BN;

    float acc[2][8][4];
#pragma unroll
    for (int mt = 0; mt < 2; mt++)
#pragma unroll
        for (int nt = 0; nt < 8; nt++)
#pragma unroll
            for (int i = 0; i < 4; i++) acc[mt][nt][i] = 0.0f;

    for (int k0 = 0; k0 < K; k0 += BK) {
        // load A tile: 128x32 = 1024 float4
#pragma unroll
        for (int i = 0; i < 4; i++) {
            int idx = tid + i * 256;
            int row = idx >> 3;     // 8 float4 per row
            int c4 = idx & 7;
            float4 v = make_float4(0.f, 0.f, 0.f, 0.f);
            int gr = blockRow + row;
            if (gr < M)
                v = *reinterpret_cast<const float4*>(A + (size_t)gr * K + k0 + c4 * 4);
            *reinterpret_cast<float4*>(&As[row][c4 * 4]) = v;
        }
        // load B tile: 32x128 = 1024 float4
#pragma unroll
        for (int i = 0; i < 4; i++) {
            int idx = tid + i * 256;
            int row = idx >> 5;     // 32 float4 per row
            int c4 = idx & 31;
            float4 v = *reinterpret_cast<const float4*>(
                B + (size_t)(k0 + row) * N + blockCol + c4 * 4);
            *reinterpret_cast<float4*>(&Bs[row][c4 * 4]) = v;
        }
        __syncthreads();

#pragma unroll
        for (int kk = 0; kk < 4; kk++) {
            const int ko = kk * 8;
            uint32_t ahi[2][4], alo[2][4];
#pragma unroll
            for (int mt = 0; mt < 2; mt++) {
                int r0 = m_base + mt * 16 + gid;
                float f0 = As[r0][ko + tig];
                float f1 = As[r0 + 8][ko + tig];
                float f2 = As[r0][ko + tig + 4];
                float f3 = As[r0 + 8][ko + tig + 4];
                split_tf32(f0, ahi[mt][0], alo[mt][0]);
                split_tf32(f1, ahi[mt][1], alo[mt][1]);
                split_tf32(f2, ahi[mt][2], alo[mt][2]);
                split_tf32(f3, ahi[mt][3], alo[mt][3]);
            }
            uint32_t bhi[8][2], blo[8][2];
#pragma unroll
            for (int nt = 0; nt < 8; nt++) {
                int col = n_base + nt * 8 + gid;
                float f0 = Bs[ko + tig][col];
                float f1 = Bs[ko + tig + 4][col];
                split_tf32(f0, bhi[nt][0], blo[nt][0]);
                split_tf32(f1, bhi[nt][1], blo[nt][1]);
            }
#pragma unroll
            for (int mt = 0; mt < 2; mt++) {
#pragma unroll
                for (int nt = 0; nt < 8; nt++) {
                    mma_tf32(acc[mt][nt], ahi[mt], bhi[nt]);   // hi*hi
                    mma_tf32(acc[mt][nt], ahi[mt], blo[nt]);   // hi*lo
                    mma_tf32(acc[mt][nt], alo[mt], bhi[nt]);   // lo*hi
                }
            }
        }
        __syncthreads();
    }

    // epilogue
#pragma unroll
    for (int mt = 0; mt < 2; mt++) {
#pragma unroll
        for (int nt = 0; nt < 8; nt++) {
            int r = blockRow + m_base + mt * 16 + gid;
            int c = blockCol + n_base + nt * 8 + tig * 2;
            if (r < M) {
                float2 v0 = make_float2(acc[mt][nt][0], acc[mt][nt][1]);
                *reinterpret_cast<float2*>(C + (size_t)r * N + c) = v0;
            }
            if (r + 8 < M) {
                float2 v1 = make_float2(acc[mt][nt][2], acc[mt][nt][3]);
                *reinterpret_cast<float2*>(C + (size_t)(r + 8) * N + c) = v1;
            }
        }
    }
}

// ---------------- gather-side aggregation (atomic-free) ----------------
// Layer 1: 256 features/node, one warp per dst node, relu + bias
__global__ void aggregate1_kernel(const float* __restrict__ bias) {
    int gw = (blockIdx.x * blockDim.x + threadIdx.x) >> 5;
    int lane = threadIdx.x & 31;
    if (gw >= N_NODES) return;
    int beg = g_rowptr[gw], end = g_rowptr[gw + 1];

    float4 a0 = make_float4(0.f, 0.f, 0.f, 0.f);
    float4 a1 = make_float4(0.f, 0.f, 0.f, 0.f);
#pragma unroll 2
    for (int e = beg; e < end; ++e) {
        int src = g_esrc[e];
        float w = g_ew[e];
        const float4* p = reinterpret_cast<const float4*>(g_hw1) + (size_t)src * 64;
        float4 v0 = p[lane];
        float4 v1 = p[lane + 32];
        a0.x += w * v0.x; a0.y += w * v0.y; a0.z += w * v0.z; a0.w += w * v0.w;
        a1.x += w * v1.x; a1.y += w * v1.y; a1.z += w * v1.z; a1.w += w * v1.w;
    }
    float inv = g_invdeg[gw];
    const float4* bp = reinterpret_cast<const float4*>(bias);
    float4 b0 = bp[lane];
    float4 b1 = bp[lane + 32];
    float4 o0, o1;
    o0.x = fmaxf(a0.x * inv + b0.x, 0.f);
    o0.y = fmaxf(a0.y * inv + b0.y, 0.f);
    o0.z = fmaxf(a0.z * inv + b0.z, 0.f);
    o0.w = fmaxf(a0.w * inv + b0.w, 0.f);
    o1.x = fmaxf(a1.x * inv + b1.x, 0.f);
    o1.y = fmaxf(a1.y * inv + b1.y, 0.f);
    o1.z = fmaxf(a1.z * inv + b1.z, 0.f);
    o1.w = fmaxf(a1.w * inv + b1.w, 0.f);
    float4* op = reinterpret_cast<float4*>(g_h) + (size_t)gw * 64;
    op[lane] = o0;
    op[lane + 32] = o1;
}

// Layer 2: 128 features/node, one warp per dst node, bias only, writes d_out
__global__ void aggregate2_kernel(const float* __restrict__ bias, float* __restrict__ out) {
    int gw = (blockIdx.x * blockDim.x + threadIdx.x) >> 5;
    int lane = threadIdx.x & 31;
    if (gw >= N_NODES) return;
    int beg = g_rowptr[gw], end = g_rowptr[gw + 1];

    float4 a0 = make_float4(0.f, 0.f, 0.f, 0.f);
#pragma unroll 2
    for (int e = beg; e < end; ++e) {
        int src = g_esrc[e];
        float w = g_ew[e];
        const float4* p = reinterpret_cast<const float4*>(g_hw2) + (size_t)src * 32;
        float4 v0 = p[lane];
        a0.x += w * v0.x; a0.y += w * v0.y; a0.z += w * v0.z; a0.w += w * v0.w;
    }
    float inv = g_invdeg[gw];
    const float4* bp = reinterpret_cast<const float4*>(bias);
    float4 b0 = bp[lane];
    float4 o0;
    o0.x = a0.x * inv + b0.x;
    o0.y = a0.y * inv + b0.y;
    o0.z = a0.z * inv + b0.z;
    o0.w = a0.w * inv + b0.w;
    float4* op = reinterpret_cast<float4*>(out) + (size_t)gw * 32;
    op[lane] = o0;
}

// ---------------- launch ----------------
extern "C" void kernel_launch(void* const* d_in, const int* in_sizes, int n_in,
                              void* d_out, int out_size) {
    const float* x    = (const float*)d_in[0];
    const float* W1   = (const float*)d_in[1];
    const float* b1   = (const float*)d_in[2];
    const float* W2   = (const float*)d_in[3];
    const float* b2   = (const float*)d_in[4];
    const float* ew   = (const float*)d_in[5];
    const int*   esrc = (const int*)d_in[6];
    const int*   edst = (const int*)d_in[7];
    float* out = (float*)d_out;

    void* p_hw1; cudaGetSymbolAddress(&p_hw1, g_hw1);
    void* p_h;   cudaGetSymbolAddress(&p_h,   g_h);
    void* p_hw2; cudaGetSymbolAddress(&p_hw2, g_hw2);

    init_kernel<<<(N_NODES + 255) / 256, 256>>>();
    count_deg_kernel<<<(N_EDGES + 255) / 256, 256>>>(edst);
    scan_kernel<<<1, 1024>>>();
    build_csr_kernel<<<(N_EDGES + 255) / 256, 256>>>(esrc, edst, ew);

    // hw1 = x @ W1   [50000,512]@[512,256]
    gemm_tf32_kernel<<<dim3(HID_F / BN, (N_NODES + BM - 1) / BM), 256>>>(
        x, W1, (float*)p_hw1, N_NODES, IN_F, HID_F);

    // h = relu(agg(hw1)*invdeg + b1)
    aggregate1_kernel<<<(N_NODES * 32 + 255) / 256, 256>>>(b1);

    // hw2 = h @ W2   [50000,256]@[256,128]
    gemm_tf32_kernel<<<dim3(OUT_F / BN, (N_NODES + BM - 1) / BM), 256>>>(
        (const float*)p_h, W2, (float*)p_hw2, N_NODES, HID_F, OUT_F);

    // out = agg(hw2)*invdeg + b2
    aggregate2_kernel<<<(N_NODES * 32 + 255) / 256, 256>>>(b2, out);
}

// round 3
// speedup vs baseline: 1.1321x; 1.1321x over previous
#include <cuda_runtime.h>
#include <cuda_bf16.h>
#include <cstdint>

#define N_NODES 50000
#define N_EDGES 850000
#define IN_F 512
#define HID_F 256
#define OUT_F 128

// ---------------- device scratch (no allocations allowed) ----------------
__device__ float g_hw1[N_NODES * HID_F];   // x @ W1
__device__ float g_h[N_NODES * HID_F];     // relu(layer1 out)
__device__ float g_hw2[N_NODES * OUT_F];   // h @ W2
__device__ float g_invdeg[N_NODES];
__device__ int   g_deg[N_NODES];
__device__ int   g_rowptr[N_NODES + 1];
__device__ int   g_pos[N_NODES];
__device__ int   g_esrc[N_EDGES];
__device__ float g_ew[N_EDGES];

// ---------------- CSR build ----------------
__global__ void count_deg_kernel(const int* __restrict__ edst) {
    int e = blockIdx.x * blockDim.x + threadIdx.x;
    if (e < N_EDGES) atomicAdd(&g_deg[edst[e]], 1);
}

// single block, 1024 threads: exclusive scan of degrees -> rowptr, plus inv_deg
__global__ void scan_kernel() {
    __shared__ int partial[1024];
    const int tid = threadIdx.x;
    const int CH = (N_NODES + 1023) / 1024;  // 49
    int start = tid * CH;
    int stop = start + CH;
    if (stop > N_NODES) stop = N_NODES;

    int s = 0;
    for (int i = start; i < stop; ++i) s += g_deg[i];
    partial[tid] = s;
    __syncthreads();
    for (int off = 1; off < 1024; off <<= 1) {
        int v = 0;
        if (tid >= off) v = partial[tid - off];
        __syncthreads();
        partial[tid] += v;
        __syncthreads();
    }
    int base = partial[tid] - s;
    for (int i = start; i < stop; ++i) {
        int d = g_deg[i];
        g_rowptr[i] = base;
        base += d;
        g_invdeg[i] = 1.0f / (float)(d > 0 ? d : 1);
    }
    if (tid == 0) g_rowptr[N_NODES] = partial[1023];
}

__global__ void build_csr_kernel(const int* __restrict__ esrc,
                                 const int* __restrict__ edst,
                                 const float* __restrict__ ew) {
    int e = blockIdx.x * blockDim.x + threadIdx.x;
    if (e >= N_EDGES) return;
    int dst = edst[e];
    int p = g_rowptr[dst] + atomicAdd(&g_pos[dst], 1);
    g_esrc[p] = esrc[e];
    g_ew[p] = ew[e];
}

// ---------------- tf32 MMA GEMM, 3-term split, cp.async double-buffered ----------------
__device__ __forceinline__ void split_tf32(float f, uint32_t& hi, uint32_t& lo) {
    uint32_t h;
    asm("cvt.rna.tf32.f32 %0, %1;" : "=r"(h) : "f"(f));
    float r = f - __uint_as_float(h);
    uint32_t l;
    asm("cvt.rna.tf32.f32 %0, %1;" : "=r"(l) : "f"(r));
    hi = h; lo = l;
}

__device__ __forceinline__ void mma_tf32(float* c, const uint32_t* a, const uint32_t* b) {
    asm volatile(
        "mma.sync.aligned.m16n8k8.row.col.f32.tf32.tf32.f32 "
        "{%0,%1,%2,%3}, {%4,%5,%6,%7}, {%8,%9}, {%0,%1,%2,%3};\n"
        : "+f"(c[0]), "+f"(c[1]), "+f"(c[2]), "+f"(c[3])
        : "r"(a[0]), "r"(a[1]), "r"(a[2]), "r"(a[3]), "r"(b[0]), "r"(b[1]));
}

__device__ __forceinline__ void cp_async16(float* smem_dst, const float* gmem_src, int src_bytes) {
    uint32_t s = (uint32_t)__cvta_generic_to_shared(smem_dst);
    asm volatile("cp.async.cg.shared.global [%0], [%1], 16, %2;\n"
                 :: "r"(s), "l"(gmem_src), "r"(src_bytes));
}
__device__ __forceinline__ void cp_commit() { asm volatile("cp.async.commit_group;\n"); }
template <int N>
__device__ __forceinline__ void cp_wait() { asm volatile("cp.async.wait_group %0;\n" :: "n"(N)); }

#define BM 128
#define BN 128
#define BK 16
#define AS_STRIDE 20    // BK + 4
#define BS_STRIDE 136   // BN + 8

// C[M,N] = A[M,K] @ B[K,N], all row-major fp32. N % 128 == 0, K % 16 == 0.
// Static shared (37.9 KB) -> no cudaFuncSetAttribute needed.
__global__ __launch_bounds__(256)
void gemm_tf32_kernel(const float* __restrict__ A, const float* __restrict__ B,
                      float* __restrict__ C, int M, int K, int N) {
    __shared__ float As[2][BM][AS_STRIDE];
    __shared__ float Bs[2][BK][BS_STRIDE];

    const int tid = threadIdx.x;
    const int wid = tid >> 5;
    const int lane = tid & 31;
    const int gid = lane >> 2;   // 0..7
    const int tig = lane & 3;    // 0..3
    const int warp_m = wid >> 1;             // 0..3
    const int warp_n = wid & 1;              // 0..1
    const int m_base = warp_m * 32;
    const int n_base = warp_n * 64;
    const int blockRow = blockIdx.y * BM;
    const int blockCol = blockIdx.x * BN;
    const int ntiles = K / BK;

    float acc[2][8][4];
#pragma unroll
    for (int mt = 0; mt < 2; mt++)
#pragma unroll
        for (int nt = 0; nt < 8; nt++)
#pragma unroll
            for (int i = 0; i < 4; i++) acc[mt][nt][i] = 0.0f;

    auto load_tiles = [&](int t, int buf) {
        const int k0 = t * BK;
        // A tile: 128x16 = 512 float4, 2 iterations
#pragma unroll
        for (int i = 0; i < 2; i++) {
            int idx = tid + i * 256;
            int row = idx >> 2;      // 4 float4 per row
            int c4 = idx & 3;
            int gr = blockRow + row;
            int inb = (gr < M);
            int grc = inb ? gr : 0;
            cp_async16(&As[buf][row][c4 * 4],
                       A + (size_t)grc * K + k0 + c4 * 4, inb ? 16 : 0);
        }
        // B tile: 16x128 = 512 float4, 2 iterations
#pragma unroll
        for (int i = 0; i < 2; i++) {
            int idx = tid + i * 256;
            int row = idx >> 5;      // 32 float4 per row
            int c4 = idx & 31;
            cp_async16(&Bs[buf][row][c4 * 4],
                       B + (size_t)(k0 + row) * N + blockCol + c4 * 4, 16);
        }
    };

    load_tiles(0, 0);
    cp_commit();

    for (int t = 0; t < ntiles; ++t) {
        const int buf = t & 1;
        if (t + 1 < ntiles) {
            load_tiles(t + 1, (t + 1) & 1);
            cp_commit();
            cp_wait<1>();
        } else {
            cp_wait<0>();
        }
        __syncthreads();

#pragma unroll
        for (int kk = 0; kk < 2; kk++) {
            const int ko = kk * 8;
            uint32_t ahi[2][4], alo[2][4];
#pragma unroll
            for (int mt = 0; mt < 2; mt++) {
                int r0 = m_base + mt * 16 + gid;
                float f0 = As[buf][r0][ko + tig];
                float f1 = As[buf][r0 + 8][ko + tig];
                float f2 = As[buf][r0][ko + tig + 4];
                float f3 = As[buf][r0 + 8][ko + tig + 4];
                split_tf32(f0, ahi[mt][0], alo[mt][0]);
                split_tf32(f1, ahi[mt][1], alo[mt][1]);
                split_tf32(f2, ahi[mt][2], alo[mt][2]);
                split_tf32(f3, ahi[mt][3], alo[mt][3]);
            }
            uint32_t bhi[8][2], blo[8][2];
#pragma unroll
            for (int nt = 0; nt < 8; nt++) {
                int col = n_base + nt * 8 + gid;
                float f0 = Bs[buf][ko + tig][col];
                float f1 = Bs[buf][ko + tig + 4][col];
                split_tf32(f0, bhi[nt][0], blo[nt][0]);
                split_tf32(f1, bhi[nt][1], blo[nt][1]);
            }
#pragma unroll
            for (int mt = 0; mt < 2; mt++) {
#pragma unroll
                for (int nt = 0; nt < 8; nt++) {
                    mma_tf32(acc[mt][nt], ahi[mt], bhi[nt]);   // hi*hi
                    mma_tf32(acc[mt][nt], ahi[mt], blo[nt]);   // hi*lo
                    mma_tf32(acc[mt][nt], alo[mt], bhi[nt]);   // lo*hi
                }
            }
        }
        __syncthreads();
    }

    // epilogue
#pragma unroll
    for (int mt = 0; mt < 2; mt++) {
#pragma unroll
        for (int nt = 0; nt < 8; nt++) {
            int r = blockRow + m_base + mt * 16 + gid;
            int c = blockCol + n_base + nt * 8 + tig * 2;
            if (r < M) {
                float2 v0 = make_float2(acc[mt][nt][0], acc[mt][nt][1]);
                *reinterpret_cast<float2*>(C + (size_t)r * N + c) = v0;
            }
            if (r + 8 < M) {
                float2 v1 = make_float2(acc[mt][nt][2], acc[mt][nt][3]);
                *reinterpret_cast<float2*>(C + (size_t)(r + 8) * N + c) = v1;
            }
        }
    }
}

// ---------------- gather-side aggregation (atomic-free) ----------------
// Layer 1: 256 feats/node, TWO warps per node (128 feats each = 1 float4/lane)
__global__ void aggregate1_kernel(const float* __restrict__ bias) {
    int gw = (blockIdx.x * blockDim.x + threadIdx.x) >> 5;
    int lane = threadIdx.x & 31;
    if (gw >= 2 * N_NODES) return;
    int node = gw >> 1;
    int half = gw & 1;           // 0: feats 0..127, 1: feats 128..255
    int beg = g_rowptr[node], end = g_rowptr[node + 1];
    int fo = lane + half * 32;   // float4 index within the 64-float4 row

    float4 a0 = make_float4(0.f, 0.f, 0.f, 0.f);
    float4 a1 = make_float4(0.f, 0.f, 0.f, 0.f);
    int e = beg;
#pragma unroll 4
    for (; e + 1 < end; e += 2) {
        int s0 = g_esrc[e];
        int s1 = g_esrc[e + 1];
        float w0 = g_ew[e];
        float w1 = g_ew[e + 1];
        float4 v0 = __ldg(reinterpret_cast<const float4*>(g_hw1) + (size_t)s0 * 64 + fo);
        float4 v1 = __ldg(reinterpret_cast<const float4*>(g_hw1) + (size_t)s1 * 64 + fo);
        a0.x += w0 * v0.x; a0.y += w0 * v0.y; a0.z += w0 * v0.z; a0.w += w0 * v0.w;
        a1.x += w1 * v1.x; a1.y += w1 * v1.y; a1.z += w1 * v1.z; a1.w += w1 * v1.w;
    }
    if (e < end) {
        int s0 = g_esrc[e];
        float w0 = g_ew[e];
        float4 v0 = __ldg(reinterpret_cast<const float4*>(g_hw1) + (size_t)s0 * 64 + fo);
        a0.x += w0 * v0.x; a0.y += w0 * v0.y; a0.z += w0 * v0.z; a0.w += w0 * v0.w;
    }
    a0.x += a1.x; a0.y += a1.y; a0.z += a1.z; a0.w += a1.w;

    float inv = g_invdeg[node];
    float4 b0 = reinterpret_cast<const float4*>(bias)[fo];
    float4 o0;
    o0.x = fmaxf(a0.x * inv + b0.x, 0.f);
    o0.y = fmaxf(a0.y * inv + b0.y, 0.f);
    o0.z = fmaxf(a0.z * inv + b0.z, 0.f);
    o0.w = fmaxf(a0.w * inv + b0.w, 0.f);
    reinterpret_cast<float4*>(g_h)[(size_t)node * 64 + fo] = o0;
}

// Layer 2: 128 feats/node, one warp per node, bias only, writes d_out
__global__ void aggregate2_kernel(const float* __restrict__ bias, float* __restrict__ out) {
    int gw = (blockIdx.x * blockDim.x + threadIdx.x) >> 5;
    int lane = threadIdx.x & 31;
    if (gw >= N_NODES) return;
    int beg = g_rowptr[gw], end = g_rowptr[gw + 1];

    float4 a0 = make_float4(0.f, 0.f, 0.f, 0.f);
    float4 a1 = make_float4(0.f, 0.f, 0.f, 0.f);
    int e = beg;
#pragma unroll 4
    for (; e + 1 < end; e += 2) {
        int s0 = g_esrc[e];
        int s1 = g_esrc[e + 1];
        float w0 = g_ew[e];
        float w1 = g_ew[e + 1];
        float4 v0 = __ldg(reinterpret_cast<const float4*>(g_hw2) + (size_t)s0 * 32 + lane);
        float4 v1 = __ldg(reinterpret_cast<const float4*>(g_hw2) + (size_t)s1 * 32 + lane);
        a0.x += w0 * v0.x; a0.y += w0 * v0.y; a0.z += w0 * v0.z; a0.w += w0 * v0.w;
        a1.x += w1 * v1.x; a1.y += w1 * v1.y; a1.z += w1 * v1.z; a1.w += w1 * v1.w;
    }
    if (e < end) {
        int s0 = g_esrc[e];
        float w0 = g_ew[e];
        float4 v0 = __ldg(reinterpret_cast<const float4*>(g_hw2) + (size_t)s0 * 32 + lane);
        a0.x += w0 * v0.x; a0.y += w0 * v0.y; a0.z += w0 * v0.z; a0.w += w0 * v0.w;
    }
    a0.x += a1.x; a0.y += a1.y; a0.z += a1.z; a0.w += a1.w;

    float inv = g_invdeg[gw];
    float4 b0 = reinterpret_cast<const float4*>(bias)[lane];
    float4 o0;
    o0.x = a0.x * inv + b0.x;
    o0.y = a0.y * inv + b0.y;
    o0.z = a0.z * inv + b0.z;
    o0.w = a0.w * inv + b0.w;
    reinterpret_cast<float4*>(out)[(size_t)gw * 32 + lane] = o0;
}

// ---------------- launch ----------------
extern "C" void kernel_launch(void* const* d_in, const int* in_sizes, int n_in,
                              void* d_out, int out_size) {
    const float* x    = (const float*)d_in[0];
    const float* W1   = (const float*)d_in[1];
    const float* b1   = (const float*)d_in[2];
    const float* W2   = (const float*)d_in[3];
    const float* b2   = (const float*)d_in[4];
    const float* ew   = (const float*)d_in[5];
    const int*   esrc = (const int*)d_in[6];
    const int*   edst = (const int*)d_in[7];
    float* out = (float*)d_out;

    void* p_hw1; cudaGetSymbolAddress(&p_hw1, g_hw1);
    void* p_h;   cudaGetSymbolAddress(&p_h,   g_h);
    void* p_hw2; cudaGetSymbolAddress(&p_hw2, g_hw2);
    void* p_deg; cudaGetSymbolAddress(&p_deg, g_deg);
    void* p_pos; cudaGetSymbolAddress(&p_pos, g_pos);

    cudaMemsetAsync(p_deg, 0, N_NODES * sizeof(int));
    cudaMemsetAsync(p_pos, 0, N_NODES * sizeof(int));
    count_deg_kernel<<<(N_EDGES + 255) / 256, 256>>>(edst);
    scan_kernel<<<1, 1024>>>();
    build_csr_kernel<<<(N_EDGES + 255) / 256, 256>>>(esrc, edst, ew);

    // hw1 = x @ W1   [50000,512]@[512,256]
    gemm_tf32_kernel<<<dim3(HID_F / BN, (N_NODES + BM - 1) / BM), 256>>>(
        x, W1, (float*)p_hw1, N_NODES, IN_F, HID_F);

    // h = relu(agg(hw1)*invdeg + b1)   (2 warps per node)
    aggregate1_kernel<<<(2 * N_NODES * 32 + 255) / 256, 256>>>(b1);

    // hw2 = h @ W2   [50000,256]@[256,128]
    gemm_tf32_kernel<<<dim3(OUT_F / BN, (N_NODES + BM - 1) / BM), 256>>>(
        (const float*)p_h, W2, (float*)p_hw2, N_NODES, HID_F, OUT_F);

    // out = agg(hw2)*invdeg + b2
    aggregate2_kernel<<<(N_NODES * 32 + 255) / 256, 256>>>(b2, out);
}

// round 4
// speedup vs baseline: 1.4541x; 1.2844x over previous
#include <cuda_runtime.h>
#include <cuda_bf16.h>
#include <cstdint>

#define N_NODES 50000
#define N_EDGES 850000
#define IN_F 512
#define HID_F 256
#define OUT_F 128

// ---------------- device scratch (no allocations allowed) ----------------
__device__ float    g_hw1[N_NODES * HID_F];        // x @ W1 (f32)
__device__ float    g_hw2[N_NODES * OUT_F];        // h @ W2 (f32)
__device__ uint32_t g_xhi[N_NODES * IN_F / 2];     // x split hi, bf16x2 packed along K
__device__ uint32_t g_xlo[N_NODES * IN_F / 2];
__device__ uint32_t g_hhi[N_NODES * HID_F / 2];    // h split hi (written by agg1)
__device__ uint32_t g_hlo[N_NODES * HID_F / 2];
__device__ uint32_t g_w1hi[(IN_F / 2) * HID_F];    // W1 k-pair-interleaved
__device__ uint32_t g_w1lo[(IN_F / 2) * HID_F];
__device__ uint32_t g_w2hi[(HID_F / 2) * OUT_F];
__device__ uint32_t g_w2lo[(HID_F / 2) * OUT_F];
__device__ float    g_invdeg[N_NODES];
__device__ int      g_deg[N_NODES];
__device__ int      g_rowptr[N_NODES + 1];
__device__ int      g_pos[N_NODES];
__device__ int      g_esrc[N_EDGES];
__device__ float    g_ew[N_EDGES];

// ---------------- bf16 split helpers ----------------
__device__ __forceinline__ void split_bf16(float v, uint16_t& hi, uint16_t& lo) {
    __nv_bfloat16 h = __float2bfloat16_rn(v);
    float r = v - __bfloat162float(h);
    __nv_bfloat16 l = __float2bfloat16_rn(r);
    hi = *reinterpret_cast<uint16_t*>(&h);
    lo = *reinterpret_cast<uint16_t*>(&l);
}
__device__ __forceinline__ uint32_t pack2(uint16_t e0, uint16_t e1) {
    return (uint32_t)e0 | ((uint32_t)e1 << 16);   // element 0 in low bits
}

// ---------------- CSR build ----------------
__global__ void count_deg_kernel(const int* __restrict__ edst) {
    int e = blockIdx.x * blockDim.x + threadIdx.x;
    if (e < N_EDGES) atomicAdd(&g_deg[edst[e]], 1);
}

__global__ void scan_kernel() {
    __shared__ int partial[1024];
    const int tid = threadIdx.x;
    const int CH = (N_NODES + 1023) / 1024;
    int start = tid * CH;
    int stop = start + CH;
    if (stop > N_NODES) stop = N_NODES;

    int s = 0;
    for (int i = start; i < stop; ++i) s += g_deg[i];
    partial[tid] = s;
    __syncthreads();
    for (int off = 1; off < 1024; off <<= 1) {
        int v = 0;
        if (tid >= off) v = partial[tid - off];
        __syncthreads();
        partial[tid] += v;
        __syncthreads();
    }
    int base = partial[tid] - s;
    for (int i = start; i < stop; ++i) {
        int d = g_deg[i];
        g_rowptr[i] = base;
        base += d;
        g_invdeg[i] = 1.0f / (float)(d > 0 ? d : 1);
    }
    if (tid == 0) g_rowptr[N_NODES] = partial[1023];
}

__global__ void build_csr_kernel(const int* __restrict__ esrc,
                                 const int* __restrict__ edst,
                                 const float* __restrict__ ew) {
    int e = blockIdx.x * blockDim.x + threadIdx.x;
    if (e >= N_EDGES) return;
    int dst = edst[e];
    int p = g_rowptr[dst] + atomicAdd(&g_pos[dst], 1);
    g_esrc[p] = esrc[e];
    g_ew[p] = ew[e];
}

// ---------------- pre-split kernels ----------------
// x (row-major [M,K]) -> packed hi/lo: pairs along K are contiguous.
__global__ void split_x_kernel(const float* __restrict__ x,
                               uint32_t* __restrict__ xh, uint32_t* __restrict__ xl,
                               int n_u32) {
    int i = blockIdx.x * blockDim.x + threadIdx.x;
    if (i >= n_u32) return;
    float2 v = reinterpret_cast<const float2*>(x)[i];
    uint16_t h0, l0, h1, l1;
    split_bf16(v.x, h0, l0);
    split_bf16(v.y, h1, l1);
    xh[i] = pack2(h0, h1);
    xl[i] = pack2(l0, l1);
}

// W (row-major [K,N]) -> k-pair-interleaved: out[k2*N + n] = (W[2k2][n], W[2k2+1][n])
__global__ void split_w_kernel(const float* __restrict__ W,
                               uint32_t* __restrict__ wh, uint32_t* __restrict__ wl,
                               int K, int N) {
    int idx = blockIdx.x * blockDim.x + threadIdx.x;
    int total = (K / 2) * N;
    if (idx >= total) return;
    int k2 = idx / N;
    int n = idx - k2 * N;
    float a = W[(size_t)(2 * k2) * N + n];
    float b = W[(size_t)(2 * k2 + 1) * N + n];
    uint16_t ha, la, hb, lb;
    split_bf16(a, ha, la);
    split_bf16(b, hb, lb);
    wh[idx] = pack2(ha, hb);
    wl[idx] = pack2(la, lb);
}

// ---------------- bf16 3-term MMA GEMM, cp.async double-buffered ----------------
__device__ __forceinline__ void mma_bf16(float* c, const uint32_t* a, const uint32_t* b) {
    asm volatile(
        "mma.sync.aligned.m16n8k16.row.col.f32.bf16.bf16.f32 "
        "{%0,%1,%2,%3}, {%4,%5,%6,%7}, {%8,%9}, {%0,%1,%2,%3};\n"
        : "+f"(c[0]), "+f"(c[1]), "+f"(c[2]), "+f"(c[3])
        : "r"(a[0]), "r"(a[1]), "r"(a[2]), "r"(a[3]), "r"(b[0]), "r"(b[1]));
}

__device__ __forceinline__ void cp_async16(void* smem_dst, const void* gmem_src, int src_bytes) {
    uint32_t s = (uint32_t)__cvta_generic_to_shared(smem_dst);
    asm volatile("cp.async.cg.shared.global [%0], [%1], 16, %2;\n"
                 :: "r"(s), "l"(gmem_src), "r"(src_bytes));
}
__device__ __forceinline__ void cp_commit() { asm volatile("cp.async.commit_group;\n"); }
template <int N>
__device__ __forceinline__ void cp_wait() { asm volatile("cp.async.wait_group %0;\n" :: "n"(N)); }

#define BM 128
#define BN 128
#define BKP 16          // K-pairs per tile (= 32 elements)
#define SA 20           // A row stride in u32 (16 data + 4 pad)
#define SB 136          // B row stride in u32 (128 data + 8 pad)
#define A_TILE (BM * SA)          // 2560 u32 per (buf,hl)
#define B_TILE (BKP * SB)         // 2176 u32 per (buf,hl)
#define SMEM_U32 (4 * A_TILE + 4 * B_TILE)   // 18944 u32 = 75776 B

// C[M,N] = A[M,2*K2] @ B[2*K2,N]; A,B given as packed bf16-pair hi/lo arrays.
// Ah/Al: [M, K2] u32 row-major. Bh/Bl: [K2, N] u32 (k-pair-interleaved).
__global__ __launch_bounds__(256, 2)
void gemm_bf16x2_kernel(const uint32_t* __restrict__ Ah, const uint32_t* __restrict__ Al,
                        const uint32_t* __restrict__ Bh, const uint32_t* __restrict__ Bl,
                        float* __restrict__ C, int M, int K2, int N) {
    extern __shared__ uint32_t smem[];
    uint32_t* Abase = smem;                    // [buf][hl][BM][SA]
    uint32_t* Bbase = smem + 4 * A_TILE;       // [buf][hl][BKP][SB]

    const int tid = threadIdx.x;
    const int wid = tid >> 5;
    const int lane = tid & 31;
    const int gid = lane >> 2;   // 0..7
    const int tig = lane & 3;    // 0..3
    const int warp_m = wid >> 1; // 0..3
    const int warp_n = wid & 1;  // 0..1
    const int m_base = warp_m * 32;
    const int n_base = warp_n * 64;
    const int blockRow = blockIdx.y * BM;
    const int blockCol = blockIdx.x * BN;
    const int ntiles = K2 / BKP;

    float acc[2][8][4];
#pragma unroll
    for (int mt = 0; mt < 2; mt++)
#pragma unroll
        for (int nt = 0; nt < 8; nt++)
#pragma unroll
            for (int i = 0; i < 4; i++) acc[mt][nt][i] = 0.0f;

    auto load_tiles = [&](int t, int buf) {
        const int k0p = t * BKP;
        const uint32_t* Ag[2] = {Ah, Al};
        const uint32_t* Bg[2] = {Bh, Bl};
#pragma unroll
        for (int hl = 0; hl < 2; hl++) {
            uint32_t* Asb = Abase + (buf * 2 + hl) * A_TILE;
            // A tile: 128 rows x 16 u32 = 512 x 16B, 2 iterations
#pragma unroll
            for (int i = 0; i < 2; i++) {
                int idx = tid + i * 256;
                int row = idx >> 2;       // 4 x 16B per row
                int c4 = idx & 3;
                int gr = blockRow + row;
                int inb = (gr < M);
                int grc = inb ? gr : 0;
                cp_async16(&Asb[row * SA + c4 * 4],
                           Ag[hl] + (size_t)grc * K2 + k0p + c4 * 4, inb ? 16 : 0);
            }
            uint32_t* Bsb = Bbase + (buf * 2 + hl) * B_TILE;
            // B tile: 16 rows x 128 u32 = 512 x 16B, 2 iterations
#pragma unroll
            for (int i = 0; i < 2; i++) {
                int idx = tid + i * 256;
                int row = idx >> 5;       // 32 x 16B per row
                int c4 = idx & 31;
                cp_async16(&Bsb[row * SB + c4 * 4],
                           Bg[hl] + (size_t)(k0p + row) * N + blockCol + c4 * 4, 16);
            }
        }
    };

    load_tiles(0, 0);
    cp_commit();

    for (int t = 0; t < ntiles; ++t) {
        const int buf = t & 1;
        if (t + 1 < ntiles) {
            load_tiles(t + 1, (t + 1) & 1);
            cp_commit();
            cp_wait<1>();
        } else {
            cp_wait<0>();
        }
        __syncthreads();

        const uint32_t* Ah_s = Abase + (buf * 2 + 0) * A_TILE;
        const uint32_t* Al_s = Abase + (buf * 2 + 1) * A_TILE;
        const uint32_t* Bh_s = Bbase + (buf * 2 + 0) * B_TILE;
        const uint32_t* Bl_s = Bbase + (buf * 2 + 1) * B_TILE;

#pragma unroll
        for (int kk = 0; kk < 2; kk++) {
            const int jb = kk * 8;   // k-pair base for this k16 step
            uint32_t ah[2][4], al[2][4];
#pragma unroll
            for (int mt = 0; mt < 2; mt++) {
                int r0 = m_base + mt * 16 + gid;
                int o0 = r0 * SA + jb + tig;
                int o1 = (r0 + 8) * SA + jb + tig;
                ah[mt][0] = Ah_s[o0];
                ah[mt][1] = Ah_s[o1];
                ah[mt][2] = Ah_s[o0 + 4];
                ah[mt][3] = Ah_s[o1 + 4];
                al[mt][0] = Al_s[o0];
                al[mt][1] = Al_s[o1];
                al[mt][2] = Al_s[o0 + 4];
                al[mt][3] = Al_s[o1 + 4];
            }
            uint32_t bh[8][2], bl[8][2];
#pragma unroll
            for (int nt = 0; nt < 8; nt++) {
                int col = n_base + nt * 8 + gid;
                int o0 = (jb + tig) * SB + col;
                int o1 = (jb + tig + 4) * SB + col;
                bh[nt][0] = Bh_s[o0];
                bh[nt][1] = Bh_s[o1];
                bl[nt][0] = Bl_s[o0];
                bl[nt][1] = Bl_s[o1];
            }
#pragma unroll
            for (int mt = 0; mt < 2; mt++) {
#pragma unroll
                for (int nt = 0; nt < 8; nt++) {
                    mma_bf16(acc[mt][nt], ah[mt], bh[nt]);   // hi*hi
                    mma_bf16(acc[mt][nt], ah[mt], bl[nt]);   // hi*lo
                    mma_bf16(acc[mt][nt], al[mt], bh[nt]);   // lo*hi
                }
            }
        }
        __syncthreads();
    }

    // epilogue
#pragma unroll
    for (int mt = 0; mt < 2; mt++) {
#pragma unroll
        for (int nt = 0; nt < 8; nt++) {
            int r = blockRow + m_base + mt * 16 + gid;
            int c = blockCol + n_base + nt * 8 + tig * 2;
            if (r < M) {
                float2 v0 = make_float2(acc[mt][nt][0], acc[mt][nt][1]);
                *reinterpret_cast<float2*>(C + (size_t)r * N + c) = v0;
            }
            if (r + 8 < M) {
                float2 v1 = make_float2(acc[mt][nt][2], acc[mt][nt][3]);
                *reinterpret_cast<float2*>(C + (size_t)(r + 8) * N + c) = v1;
            }
        }
    }
}

// ---------------- gather-side aggregation (atomic-free) ----------------
// Layer 1: 256 feats/node, TWO warps per node. Emits h pre-split as bf16 pairs.
__global__ void aggregate1_kernel(const float* __restrict__ bias) {
    int gw = (blockIdx.x * blockDim.x + threadIdx.x) >> 5;
    int lane = threadIdx.x & 31;
    if (gw >= 2 * N_NODES) return;
    int node = gw >> 1;
    int half = gw & 1;
    int beg = g_rowptr[node], end = g_rowptr[node + 1];
    int fo = lane + half * 32;   // float4 index within the 64-float4 row

    float4 a0 = make_float4(0.f, 0.f, 0.f, 0.f);
    float4 a1 = make_float4(0.f, 0.f, 0.f, 0.f);
    int e = beg;
#pragma unroll 4
    for (; e + 1 < end; e += 2) {
        int s0 = g_esrc[e];
        int s1 = g_esrc[e + 1];
        float w0 = g_ew[e];
        float w1 = g_ew[e + 1];
        float4 v0 = __ldg(reinterpret_cast<const float4*>(g_hw1) + (size_t)s0 * 64 + fo);
        float4 v1 = __ldg(reinterpret_cast<const float4*>(g_hw1) + (size_t)s1 * 64 + fo);
        a0.x += w0 * v0.x; a0.y += w0 * v0.y; a0.z += w0 * v0.z; a0.w += w0 * v0.w;
        a1.x += w1 * v1.x; a1.y += w1 * v1.y; a1.z += w1 * v1.z; a1.w += w1 * v1.w;
    }
    if (e < end) {
        int s0 = g_esrc[e];
        float w0 = g_ew[e];
        float4 v0 = __ldg(reinterpret_cast<const float4*>(g_hw1) + (size_t)s0 * 64 + fo);
        a0.x += w0 * v0.x; a0.y += w0 * v0.y; a0.z += w0 * v0.z; a0.w += w0 * v0.w;
    }
    a0.x += a1.x; a0.y += a1.y; a0.z += a1.z; a0.w += a1.w;

    float inv = g_invdeg[node];
    float4 b0 = reinterpret_cast<const float4*>(bias)[fo];
    float o0 = fmaxf(a0.x * inv + b0.x, 0.f);
    float o1 = fmaxf(a0.y * inv + b0.y, 0.f);
    float o2 = fmaxf(a0.z * inv + b0.z, 0.f);
    float o3 = fmaxf(a0.w * inv + b0.w, 0.f);

    uint16_t h0, l0, h1, l1, h2, l2, h3, l3;
    split_bf16(o0, h0, l0);
    split_bf16(o1, h1, l1);
    split_bf16(o2, h2, l2);
    split_bf16(o3, h3, l3);
    uint2 ph = make_uint2(pack2(h0, h1), pack2(h2, h3));
    uint2 pl = make_uint2(pack2(l0, l1), pack2(l2, l3));
    size_t oidx = (size_t)node * 64 + fo;   // uint2 index (= float4 index)
    reinterpret_cast<uint2*>(g_hhi)[oidx] = ph;
    reinterpret_cast<uint2*>(g_hlo)[oidx] = pl;
}

// Layer 2: 128 feats/node, one warp per node, bias only, writes d_out (f32)
__global__ void aggregate2_kernel(const float* __restrict__ bias, float* __restrict__ out) {
    int gw = (blockIdx.x * blockDim.x + threadIdx.x) >> 5;
    int lane = threadIdx.x & 31;
    if (gw >= N_NODES) return;
    int beg = g_rowptr[gw], end = g_rowptr[gw + 1];

    float4 a0 = make_float4(0.f, 0.f, 0.f, 0.f);
    float4 a1 = make_float4(0.f, 0.f, 0.f, 0.f);
    int e = beg;
#pragma unroll 4
    for (; e + 1 < end; e += 2) {
        int s0 = g_esrc[e];
        int s1 = g_esrc[e + 1];
        float w0 = g_ew[e];
        float w1 = g_ew[e + 1];
        float4 v0 = __ldg(reinterpret_cast<const float4*>(g_hw2) + (size_t)s0 * 32 + lane);
        float4 v1 = __ldg(reinterpret_cast<const float4*>(g_hw2) + (size_t)s1 * 32 + lane);
        a0.x += w0 * v0.x; a0.y += w0 * v0.y; a0.z += w0 * v0.z; a0.w += w0 * v0.w;
        a1.x += w1 * v1.x; a1.y += w1 * v1.y; a1.z += w1 * v1.z; a1.w += w1 * v1.w;
    }
    if (e < end) {
        int s0 = g_esrc[e];
        float w0 = g_ew[e];
        float4 v0 = __ldg(reinterpret_cast<const float4*>(g_hw2) + (size_t)s0 * 32 + lane);
        a0.x += w0 * v0.x; a0.y += w0 * v0.y; a0.z += w0 * v0.z; a0.w += w0 * v0.w;
    }
    a0.x += a1.x; a0.y += a1.y; a0.z += a1.z; a0.w += a1.w;

    float inv = g_invdeg[gw];
    float4 b0 = reinterpret_cast<const float4*>(bias)[lane];
    float4 o0;
    o0.x = a0.x * inv + b0.x;
    o0.y = a0.y * inv + b0.y;
    o0.z = a0.z * inv + b0.z;
    o0.w = a0.w * inv + b0.w;
    reinterpret_cast<float4*>(out)[(size_t)gw * 32 + lane] = o0;
}

// ---------------- launch ----------------
extern "C" void kernel_launch(void* const* d_in, const int* in_sizes, int n_in,
                              void* d_out, int out_size) {
    const float* x    = (const float*)d_in[0];
    const float* W1   = (const float*)d_in[1];
    const float* b1   = (const float*)d_in[2];
    const float* W2   = (const float*)d_in[3];
    const float* b2   = (const float*)d_in[4];
    const float* ew   = (const float*)d_in[5];
    const int*   esrc = (const int*)d_in[6];
    const int*   edst = (const int*)d_in[7];
    float* out = (float*)d_out;

    void *p_hw1, *p_hw2, *p_xhi, *p_xlo, *p_hhi, *p_hlo;
    void *p_w1hi, *p_w1lo, *p_w2hi, *p_w2lo, *p_deg, *p_pos;
    cudaGetSymbolAddress(&p_hw1, g_hw1);
    cudaGetSymbolAddress(&p_hw2, g_hw2);
    cudaGetSymbolAddress(&p_xhi, g_xhi);
    cudaGetSymbolAddress(&p_xlo, g_xlo);
    cudaGetSymbolAddress(&p_hhi, g_hhi);
    cudaGetSymbolAddress(&p_hlo, g_hlo);
    cudaGetSymbolAddress(&p_w1hi, g_w1hi);
    cudaGetSymbolAddress(&p_w1lo, g_w1lo);
    cudaGetSymbolAddress(&p_w2hi, g_w2hi);
    cudaGetSymbolAddress(&p_w2lo, g_w2lo);
    cudaGetSymbolAddress(&p_deg, g_deg);
    cudaGetSymbolAddress(&p_pos, g_pos);

    cudaFuncSetAttribute(gemm_bf16x2_kernel,
                         cudaFuncAttributeMaxDynamicSharedMemorySize, SMEM_U32 * 4);

    cudaMemsetAsync(p_deg, 0, N_NODES * sizeof(int));
    cudaMemsetAsync(p_pos, 0, N_NODES * sizeof(int));

    // pre-splits (independent of CSR build)
    {
        int n_u32 = N_NODES * IN_F / 2;
        split_x_kernel<<<(n_u32 + 255) / 256, 256>>>(x, (uint32_t*)p_xhi, (uint32_t*)p_xlo, n_u32);
    }
    split_w_kernel<<<((IN_F / 2) * HID_F + 255) / 256, 256>>>(
        W1, (uint32_t*)p_w1hi, (uint32_t*)p_w1lo, IN_F, HID_F);
    split_w_kernel<<<((HID_F / 2) * OUT_F + 255) / 256, 256>>>(
        W2, (uint32_t*)p_w2hi, (uint32_t*)p_w2lo, HID_F, OUT_F);

    count_deg_kernel<<<(N_EDGES + 255) / 256, 256>>>(edst);
    scan_kernel<<<1, 1024>>>();
    build_csr_kernel<<<(N_EDGES + 255) / 256, 256>>>(esrc, edst, ew);

    // hw1 = x @ W1   [50000,512]@[512,256]
    gemm_bf16x2_kernel<<<dim3(HID_F / BN, (N_NODES + BM - 1) / BM), 256, SMEM_U32 * 4>>>(
        (const uint32_t*)p_xhi, (const uint32_t*)p_xlo,
        (const uint32_t*)p_w1hi, (const uint32_t*)p_w1lo,
        (float*)p_hw1, N_NODES, IN_F / 2, HID_F);

    // h = relu(agg(hw1)*invdeg + b1), emitted pre-split (2 warps per node)
    aggregate1_kernel<<<(2 * N_NODES * 32 + 255) / 256, 256>>>(b1);

    // hw2 = h @ W2   [50000,256]@[256,128]
    gemm_bf16x2_kernel<<<dim3(OUT_F / BN, (N_NODES + BM - 1) / BM), 256, SMEM_U32 * 4>>>(
        (const uint32_t*)p_hhi, (const uint32_t*)p_hlo,
        (const uint32_t*)p_w2hi, (const uint32_t*)p_w2lo,
        (float*)p_hw2, N_NODES, HID_F / 2, OUT_F);

    // out = agg(hw2)*invdeg + b2
    aggregate2_kernel<<<(N_NODES * 32 + 255) / 256, 256>>>(b2, out);
}

// round 5
// speedup vs baseline: 1.5626x; 1.0746x over previous
#include <cuda_runtime.h>
#include <cuda_bf16.h>
#include <cuda_fp16.h>
#include <cstdint>

#define N_NODES 50000
#define N_EDGES 850000
#define IN_F 512
#define HID_F 256
#define OUT_F 128

// ---------------- device scratch (no allocations allowed) ----------------
__device__ uint32_t g_hw1h[N_NODES * HID_F / 2];   // x @ W1, fp16x2 packed
__device__ uint32_t g_hw2h[N_NODES * OUT_F / 2];   // h @ W2, fp16x2 packed
__device__ uint32_t g_xhi[N_NODES * IN_F / 2];     // x split hi, bf16x2 packed along K
__device__ uint32_t g_xlo[N_NODES * IN_F / 2];
__device__ uint32_t g_hhi[N_NODES * HID_F / 2];    // h split hi (written by agg1)
__device__ uint32_t g_hlo[N_NODES * HID_F / 2];
__device__ uint32_t g_w1hi[(IN_F / 2) * HID_F];    // W1 k-pair-interleaved
__device__ uint32_t g_w1lo[(IN_F / 2) * HID_F];
__device__ uint32_t g_w2hi[(HID_F / 2) * OUT_F];
__device__ uint32_t g_w2lo[(HID_F / 2) * OUT_F];
__device__ float    g_invdeg[N_NODES];
__device__ int      g_deg[N_NODES];
__device__ int      g_rowptr[N_NODES + 1];
__device__ int      g_pos[N_NODES];
__device__ int      g_esrc[N_EDGES];
__device__ float    g_ew[N_EDGES];

// ---------------- bf16 split helpers ----------------
__device__ __forceinline__ void split_bf16(float v, uint16_t& hi, uint16_t& lo) {
    __nv_bfloat16 h = __float2bfloat16_rn(v);
    float r = v - __bfloat162float(h);
    __nv_bfloat16 l = __float2bfloat16_rn(r);
    hi = *reinterpret_cast<uint16_t*>(&h);
    lo = *reinterpret_cast<uint16_t*>(&l);
}
__device__ __forceinline__ uint32_t pack2(uint16_t e0, uint16_t e1) {
    return (uint32_t)e0 | ((uint32_t)e1 << 16);   // element 0 in low bits
}
__device__ __forceinline__ uint32_t split_pair_hi(float a, float b, uint32_t& lo_out) {
    uint16_t ha, la, hb, lb;
    split_bf16(a, ha, la);
    split_bf16(b, hb, lb);
    lo_out = pack2(la, lb);
    return pack2(ha, hb);
}

// ---------------- CSR build ----------------
__global__ void count_deg_kernel(const int* __restrict__ edst) {
    int e = blockIdx.x * blockDim.x + threadIdx.x;
    if (e < N_EDGES) atomicAdd(&g_deg[edst[e]], 1);
}

__global__ void scan_kernel() {
    __shared__ int partial[1024];
    const int tid = threadIdx.x;
    const int CH = (N_NODES + 1023) / 1024;
    int start = tid * CH;
    int stop = start + CH;
    if (stop > N_NODES) stop = N_NODES;

    int s = 0;
    for (int i = start; i < stop; ++i) s += g_deg[i];
    partial[tid] = s;
    __syncthreads();
    for (int off = 1; off < 1024; off <<= 1) {
        int v = 0;
        if (tid >= off) v = partial[tid - off];
        __syncthreads();
        partial[tid] += v;
        __syncthreads();
    }
    int base = partial[tid] - s;
    for (int i = start; i < stop; ++i) {
        int d = g_deg[i];
        g_rowptr[i] = base;
        base += d;
        g_invdeg[i] = 1.0f / (float)(d > 0 ? d : 1);
    }
    if (tid == 0) g_rowptr[N_NODES] = partial[1023];
}

__global__ void build_csr_kernel(const int* __restrict__ esrc,
                                 const int* __restrict__ edst,
                                 const float* __restrict__ ew) {
    int e = blockIdx.x * blockDim.x + threadIdx.x;
    if (e >= N_EDGES) return;
    int dst = edst[e];
    int p = g_rowptr[dst] + atomicAdd(&g_pos[dst], 1);
    g_esrc[p] = esrc[e];
    g_ew[p] = ew[e];
}

// ---------------- pre-split kernels ----------------
__global__ void split_x_kernel(const float* __restrict__ x,
                               uint32_t* __restrict__ xh, uint32_t* __restrict__ xl,
                               int n_u32) {
    int i = blockIdx.x * blockDim.x + threadIdx.x;
    if (i >= n_u32) return;
    float2 v = reinterpret_cast<const float2*>(x)[i];
    uint32_t lo;
    uint32_t hi = split_pair_hi(v.x, v.y, lo);
    xh[i] = hi;
    xl[i] = lo;
}

// W (row-major [K,N]) -> k-pair-interleaved: out[k2*N + n] = (W[2k2][n], W[2k2+1][n])
__global__ void split_w_kernel(const float* __restrict__ W,
                               uint32_t* __restrict__ wh, uint32_t* __restrict__ wl,
                               int K, int N) {
    int idx = blockIdx.x * blockDim.x + threadIdx.x;
    int total = (K / 2) * N;
    if (idx >= total) return;
    int k2 = idx / N;
    int n = idx - k2 * N;
    float a = W[(size_t)(2 * k2) * N + n];
    float b = W[(size_t)(2 * k2 + 1) * N + n];
    uint32_t lo;
    uint32_t hi = split_pair_hi(a, b, lo);
    wh[idx] = hi;
    wl[idx] = lo;
}

// ---------------- bf16 3-term MMA GEMM, cp.async double-buffered, fp16 output ----------------
__device__ __forceinline__ void mma_bf16(float* c, const uint32_t* a, const uint32_t* b) {
    asm volatile(
        "mma.sync.aligned.m16n8k16.row.col.f32.bf16.bf16.f32 "
        "{%0,%1,%2,%3}, {%4,%5,%6,%7}, {%8,%9}, {%0,%1,%2,%3};\n"
        : "+f"(c[0]), "+f"(c[1]), "+f"(c[2]), "+f"(c[3])
        : "r"(a[0]), "r"(a[1]), "r"(a[2]), "r"(a[3]), "r"(b[0]), "r"(b[1]));
}

__device__ __forceinline__ void cp_async16(void* smem_dst, const void* gmem_src, int src_bytes) {
    uint32_t s = (uint32_t)__cvta_generic_to_shared(smem_dst);
    asm volatile("cp.async.cg.shared.global [%0], [%1], 16, %2;\n"
                 :: "r"(s), "l"(gmem_src), "r"(src_bytes));
}
__device__ __forceinline__ void cp_commit() { asm volatile("cp.async.commit_group;\n"); }
template <int N>
__device__ __forceinline__ void cp_wait() { asm volatile("cp.async.wait_group %0;\n" :: "n"(N)); }

#define BM 128
#define BN 128
#define BKP 16          // K-pairs per tile (= 32 elements)
#define SA 20           // A row stride in u32
#define SB 136          // B row stride in u32
#define A_TILE (BM * SA)
#define B_TILE (BKP * SB)
#define SMEM_U32 (4 * A_TILE + 4 * B_TILE)   // 75776 B

// C (fp16x2 packed) = A[M,2*K2] @ B[2*K2,N]; inputs are packed bf16-pair hi/lo arrays.
__global__ __launch_bounds__(256, 2)
void gemm_bf16x2_kernel(const uint32_t* __restrict__ Ah, const uint32_t* __restrict__ Al,
                        const uint32_t* __restrict__ Bh, const uint32_t* __restrict__ Bl,
                        uint32_t* __restrict__ Ch, int M, int K2, int N) {
    extern __shared__ uint32_t smem[];
    uint32_t* Abase = smem;                    // [buf][hl][BM][SA]
    uint32_t* Bbase = smem + 4 * A_TILE;       // [buf][hl][BKP][SB]

    const int tid = threadIdx.x;
    const int wid = tid >> 5;
    const int lane = tid & 31;
    const int gid = lane >> 2;
    const int tig = lane & 3;
    const int warp_m = wid >> 1;
    const int warp_n = wid & 1;
    const int m_base = warp_m * 32;
    const int n_base = warp_n * 64;
    const int blockRow = blockIdx.y * BM;
    const int blockCol = blockIdx.x * BN;
    const int ntiles = K2 / BKP;

    float acc[2][8][4];
#pragma unroll
    for (int mt = 0; mt < 2; mt++)
#pragma unroll
        for (int nt = 0; nt < 8; nt++)
#pragma unroll
            for (int i = 0; i < 4; i++) acc[mt][nt][i] = 0.0f;

    auto load_tiles = [&](int t, int buf) {
        const int k0p = t * BKP;
        const uint32_t* Ag[2] = {Ah, Al};
        const uint32_t* Bg[2] = {Bh, Bl};
#pragma unroll
        for (int hl = 0; hl < 2; hl++) {
            uint32_t* Asb = Abase + (buf * 2 + hl) * A_TILE;
#pragma unroll
            for (int i = 0; i < 2; i++) {
                int idx = tid + i * 256;
                int row = idx >> 2;
                int c4 = idx & 3;
                int gr = blockRow + row;
                int inb = (gr < M);
                int grc = inb ? gr : 0;
                cp_async16(&Asb[row * SA + c4 * 4],
                           Ag[hl] + (size_t)grc * K2 + k0p + c4 * 4, inb ? 16 : 0);
            }
            uint32_t* Bsb = Bbase + (buf * 2 + hl) * B_TILE;
#pragma unroll
            for (int i = 0; i < 2; i++) {
                int idx = tid + i * 256;
                int row = idx >> 5;
                int c4 = idx & 31;
                cp_async16(&Bsb[row * SB + c4 * 4],
                           Bg[hl] + (size_t)(k0p + row) * N + blockCol + c4 * 4, 16);
            }
        }
    };

    load_tiles(0, 0);
    cp_commit();

    for (int t = 0; t < ntiles; ++t) {
        const int buf = t & 1;
        if (t + 1 < ntiles) {
            load_tiles(t + 1, (t + 1) & 1);
            cp_commit();
            cp_wait<1>();
        } else {
            cp_wait<0>();
        }
        __syncthreads();

        const uint32_t* Ah_s = Abase + (buf * 2 + 0) * A_TILE;
        const uint32_t* Al_s = Abase + (buf * 2 + 1) * A_TILE;
        const uint32_t* Bh_s = Bbase + (buf * 2 + 0) * B_TILE;
        const uint32_t* Bl_s = Bbase + (buf * 2 + 1) * B_TILE;

#pragma unroll
        for (int kk = 0; kk < 2; kk++) {
            const int jb = kk * 8;
            uint32_t ah[2][4], al[2][4];
#pragma unroll
            for (int mt = 0; mt < 2; mt++) {
                int r0 = m_base + mt * 16 + gid;
                int o0 = r0 * SA + jb + tig;
                int o1 = (r0 + 8) * SA + jb + tig;
                ah[mt][0] = Ah_s[o0];
                ah[mt][1] = Ah_s[o1];
                ah[mt][2] = Ah_s[o0 + 4];
                ah[mt][3] = Ah_s[o1 + 4];
                al[mt][0] = Al_s[o0];
                al[mt][1] = Al_s[o1];
                al[mt][2] = Al_s[o0 + 4];
                al[mt][3] = Al_s[o1 + 4];
            }
            uint32_t bh[8][2], bl[8][2];
#pragma unroll
            for (int nt = 0; nt < 8; nt++) {
                int col = n_base + nt * 8 + gid;
                int o0 = (jb + tig) * SB + col;
                int o1 = (jb + tig + 4) * SB + col;
                bh[nt][0] = Bh_s[o0];
                bh[nt][1] = Bh_s[o1];
                bl[nt][0] = Bl_s[o0];
                bl[nt][1] = Bl_s[o1];
            }
#pragma unroll
            for (int mt = 0; mt < 2; mt++) {
#pragma unroll
                for (int nt = 0; nt < 8; nt++) {
                    mma_bf16(acc[mt][nt], ah[mt], bh[nt]);
                    mma_bf16(acc[mt][nt], ah[mt], bl[nt]);
                    mma_bf16(acc[mt][nt], al[mt], bh[nt]);
                }
            }
        }
        __syncthreads();
    }

    // epilogue: pack adjacent column pairs to fp16x2
#pragma unroll
    for (int mt = 0; mt < 2; mt++) {
#pragma unroll
        for (int nt = 0; nt < 8; nt++) {
            int r = blockRow + m_base + mt * 16 + gid;
            int c = blockCol + n_base + nt * 8 + tig * 2;
            if (r < M) {
                __half2 p = __floats2half2_rn(acc[mt][nt][0], acc[mt][nt][1]);
                Ch[((size_t)r * N + c) >> 1] = *reinterpret_cast<uint32_t*>(&p);
            }
            if (r + 8 < M) {
                __half2 p = __floats2half2_rn(acc[mt][nt][2], acc[mt][nt][3]);
                Ch[((size_t)(r + 8) * N + c) >> 1] = *reinterpret_cast<uint32_t*>(&p);
            }
        }
    }
}

// ---------------- gather-side aggregation (fp16 features, f32 accum) ----------------
__device__ __forceinline__ void acc_fma8(float* a, uint4 v, float w) {
    float2 p;
    p = __half22float2(*reinterpret_cast<__half2*>(&v.x)); a[0] += w * p.x; a[1] += w * p.y;
    p = __half22float2(*reinterpret_cast<__half2*>(&v.y)); a[2] += w * p.x; a[3] += w * p.y;
    p = __half22float2(*reinterpret_cast<__half2*>(&v.z)); a[4] += w * p.x; a[5] += w * p.y;
    p = __half22float2(*reinterpret_cast<__half2*>(&v.w)); a[6] += w * p.x; a[7] += w * p.y;
}

// Layer 1: 256 fp16 feats/node = 512B row = one uint4 per lane. One warp per node.
// Emits h pre-split as bf16 hi/lo pairs for GEMM2.
__global__ void aggregate1_kernel(const float* __restrict__ bias) {
    int gw = (blockIdx.x * blockDim.x + threadIdx.x) >> 5;
    int lane = threadIdx.x & 31;
    if (gw >= N_NODES) return;
    int beg = g_rowptr[gw], end = g_rowptr[gw + 1];

    float a[8];
#pragma unroll
    for (int i = 0; i < 8; i++) a[i] = 0.0f;

    const uint4* feat = reinterpret_cast<const uint4*>(g_hw1h);
    int e = beg;
    for (; e + 1 < end; e += 2) {
        int s0 = g_esrc[e];
        int s1 = g_esrc[e + 1];
        float w0 = g_ew[e];
        float w1 = g_ew[e + 1];
        uint4 v0 = __ldg(feat + (size_t)s0 * 32 + lane);
        uint4 v1 = __ldg(feat + (size_t)s1 * 32 + lane);
        acc_fma8(a, v0, w0);
        acc_fma8(a, v1, w1);
    }
    if (e < end) {
        int s0 = g_esrc[e];
        float w0 = g_ew[e];
        uint4 v0 = __ldg(feat + (size_t)s0 * 32 + lane);
        acc_fma8(a, v0, w0);
    }

    float inv = g_invdeg[gw];
    const float4* bp = reinterpret_cast<const float4*>(bias);
    float4 bA = bp[lane * 2];
    float4 bB = bp[lane * 2 + 1];
    float o[8];
    o[0] = fmaxf(a[0] * inv + bA.x, 0.f);
    o[1] = fmaxf(a[1] * inv + bA.y, 0.f);
    o[2] = fmaxf(a[2] * inv + bA.z, 0.f);
    o[3] = fmaxf(a[3] * inv + bA.w, 0.f);
    o[4] = fmaxf(a[4] * inv + bB.x, 0.f);
    o[5] = fmaxf(a[5] * inv + bB.y, 0.f);
    o[6] = fmaxf(a[6] * inv + bB.z, 0.f);
    o[7] = fmaxf(a[7] * inv + bB.w, 0.f);

    uint4 ph, pl;
    ph.x = split_pair_hi(o[0], o[1], pl.x);
    ph.y = split_pair_hi(o[2], o[3], pl.y);
    ph.z = split_pair_hi(o[4], o[5], pl.z);
    ph.w = split_pair_hi(o[6], o[7], pl.w);
    size_t oidx = (size_t)gw * 32 + lane;
    reinterpret_cast<uint4*>(g_hhi)[oidx] = ph;
    reinterpret_cast<uint4*>(g_hlo)[oidx] = pl;
}

// Layer 2: 128 fp16 feats/node = 256B row = one uint2 per lane. One warp per node.
__global__ void aggregate2_kernel(const float* __restrict__ bias, float* __restrict__ out) {
    int gw = (blockIdx.x * blockDim.x + threadIdx.x) >> 5;
    int lane = threadIdx.x & 31;
    if (gw >= N_NODES) return;
    int beg = g_rowptr[gw], end = g_rowptr[gw + 1];

    float a[4];
#pragma unroll
    for (int i = 0; i < 4; i++) a[i] = 0.0f;

    const uint2* feat = reinterpret_cast<const uint2*>(g_hw2h);
    int e = beg;
    for (; e + 1 < end; e += 2) {
        int s0 = g_esrc[e];
        int s1 = g_esrc[e + 1];
        float w0 = g_ew[e];
        float w1 = g_ew[e + 1];
        uint2 v0 = __ldg(feat + (size_t)s0 * 32 + lane);
        uint2 v1 = __ldg(feat + (size_t)s1 * 32 + lane);
        float2 p;
        p = __half22float2(*reinterpret_cast<__half2*>(&v0.x)); a[0] += w0 * p.x; a[1] += w0 * p.y;
        p = __half22float2(*reinterpret_cast<__half2*>(&v0.y)); a[2] += w0 * p.x; a[3] += w0 * p.y;
        p = __half22float2(*reinterpret_cast<__half2*>(&v1.x)); a[0] += w1 * p.x; a[1] += w1 * p.y;
        p = __half22float2(*reinterpret_cast<__half2*>(&v1.y)); a[2] += w1 * p.x; a[3] += w1 * p.y;
    }
    if (e < end) {
        int s0 = g_esrc[e];
        float w0 = g_ew[e];
        uint2 v0 = __ldg(feat + (size_t)s0 * 32 + lane);
        float2 p;
        p = __half22float2(*reinterpret_cast<__half2*>(&v0.x)); a[0] += w0 * p.x; a[1] += w0 * p.y;
        p = __half22float2(*reinterpret_cast<__half2*>(&v0.y)); a[2] += w0 * p.x; a[3] += w0 * p.y;
    }

    float inv = g_invdeg[gw];
    float4 b0 = reinterpret_cast<const float4*>(bias)[lane];
    float4 o0;
    o0.x = a[0] * inv + b0.x;
    o0.y = a[1] * inv + b0.y;
    o0.z = a[2] * inv + b0.z;
    o0.w = a[3] * inv + b0.w;
    reinterpret_cast<float4*>(out)[(size_t)gw * 32 + lane] = o0;
}

// ---------------- launch ----------------
extern "C" void kernel_launch(void* const* d_in, const int* in_sizes, int n_in,
                              void* d_out, int out_size) {
    const float* x    = (const float*)d_in[0];
    const float* W1   = (const float*)d_in[1];
    const float* b1   = (const float*)d_in[2];
    const float* W2   = (const float*)d_in[3];
    const float* b2   = (const float*)d_in[4];
    const float* ew   = (const float*)d_in[5];
    const int*   esrc = (const int*)d_in[6];
    const int*   edst = (const int*)d_in[7];
    float* out = (float*)d_out;

    void *p_hw1h, *p_hw2h, *p_xhi, *p_xlo, *p_hhi, *p_hlo;
    void *p_w1hi, *p_w1lo, *p_w2hi, *p_w2lo, *p_deg, *p_pos;
    cudaGetSymbolAddress(&p_hw1h, g_hw1h);
    cudaGetSymbolAddress(&p_hw2h, g_hw2h);
    cudaGetSymbolAddress(&p_xhi, g_xhi);
    cudaGetSymbolAddress(&p_xlo, g_xlo);
    cudaGetSymbolAddress(&p_hhi, g_hhi);
    cudaGetSymbolAddress(&p_hlo, g_hlo);
    cudaGetSymbolAddress(&p_w1hi, g_w1hi);
    cudaGetSymbolAddress(&p_w1lo, g_w1lo);
    cudaGetSymbolAddress(&p_w2hi, g_w2hi);
    cudaGetSymbolAddress(&p_w2lo, g_w2lo);
    cudaGetSymbolAddress(&p_deg, g_deg);
    cudaGetSymbolAddress(&p_pos, g_pos);

    cudaFuncSetAttribute(gemm_bf16x2_kernel,
                         cudaFuncAttributeMaxDynamicSharedMemorySize, SMEM_U32 * 4);

    cudaMemsetAsync(p_deg, 0, N_NODES * sizeof(int));
    cudaMemsetAsync(p_pos, 0, N_NODES * sizeof(int));

    {
        int n_u32 = N_NODES * IN_F / 2;
        split_x_kernel<<<(n_u32 + 255) / 256, 256>>>(x, (uint32_t*)p_xhi, (uint32_t*)p_xlo, n_u32);
    }
    split_w_kernel<<<((IN_F / 2) * HID_F + 255) / 256, 256>>>(
        W1, (uint32_t*)p_w1hi, (uint32_t*)p_w1lo, IN_F, HID_F);
    split_w_kernel<<<((HID_F / 2) * OUT_F + 255) / 256, 256>>>(
        W2, (uint32_t*)p_w2hi, (uint32_t*)p_w2lo, HID_F, OUT_F);

    count_deg_kernel<<<(N_EDGES + 255) / 256, 256>>>(edst);
    scan_kernel<<<1, 1024>>>();
    build_csr_kernel<<<(N_EDGES + 255) / 256, 256>>>(esrc, edst, ew);

    // hw1 = x @ W1 -> fp16
    gemm_bf16x2_kernel<<<dim3(HID_F / BN, (N_NODES + BM - 1) / BM), 256, SMEM_U32 * 4>>>(
        (const uint32_t*)p_xhi, (const uint32_t*)p_xlo,
        (const uint32_t*)p_w1hi, (const uint32_t*)p_w1lo,
        (uint32_t*)p_hw1h, N_NODES, IN_F / 2, HID_F);

    // h = relu(agg(hw1)*invdeg + b1), emitted pre-split (1 warp per node)
    aggregate1_kernel<<<(N_NODES * 32 + 255) / 256, 256>>>(b1);

    // hw2 = h @ W2 -> fp16
    gemm_bf16x2_kernel<<<dim3(OUT_F / BN, (N_NODES + BM - 1) / BM), 256, SMEM_U32 * 4>>>(
        (const uint32_t*)p_hhi, (const uint32_t*)p_hlo,
        (const uint32_t*)p_w2hi, (const uint32_t*)p_w2lo,
        (uint32_t*)p_hw2h, N_NODES, HID_F / 2, OUT_F);

    // out = agg(hw2)*invdeg + b2
    aggregate2_kernel<<<(N_NODES * 32 + 255) / 256, 256>>>(b2, out);
}

// round 7
// speedup vs baseline: 1.7242x; 1.1034x over previous
#include <cuda_runtime.h>
#include <cuda_bf16.h>
#include <cuda_fp16.h>
#include <cstdint>

#define N_NODES 50000
#define N_EDGES 850000
#define IN_F 512
#define HID_F 256
#define OUT_F 128

// ---------------- device scratch (no allocations allowed) ----------------
__device__ uint32_t g_hw1h[N_NODES * HID_F / 2];   // x @ W1, fp16x2 packed
__device__ uint32_t g_hw2h[N_NODES * OUT_F / 2];   // h @ W2, fp16x2 packed
__device__ uint32_t g_xhi[N_NODES * IN_F / 2];     // x split hi, bf16x2 packed along K
__device__ uint32_t g_xlo[N_NODES * IN_F / 2];
__device__ uint32_t g_hhi[N_NODES * HID_F / 2];    // h split hi (written by agg1)
__device__ uint32_t g_hlo[N_NODES * HID_F / 2];
__device__ uint32_t g_w1hi[(IN_F / 2) * HID_F];    // W1 k-pair-interleaved
__device__ uint32_t g_w1lo[(IN_F / 2) * HID_F];
__device__ uint32_t g_w2hi[(HID_F / 2) * OUT_F];
__device__ uint32_t g_w2lo[(HID_F / 2) * OUT_F];
__device__ float    g_invdeg[N_NODES];
__device__ int      g_deg[N_NODES];
__device__ int      g_rowptr[N_NODES + 1];
__device__ int      g_pos[N_NODES];
__device__ int      g_esrc[N_EDGES];
__device__ float    g_ew[N_EDGES];

// ---------------- bf16 split helpers ----------------
__device__ __forceinline__ void split_bf16(float v, uint16_t& hi, uint16_t& lo) {
    __nv_bfloat16 h = __float2bfloat16_rn(v);
    float r = v - __bfloat162float(h);
    __nv_bfloat16 l = __float2bfloat16_rn(r);
    hi = *reinterpret_cast<uint16_t*>(&h);
    lo = *reinterpret_cast<uint16_t*>(&l);
}
__device__ __forceinline__ uint32_t pack2(uint16_t e0, uint16_t e1) {
    return (uint32_t)e0 | ((uint32_t)e1 << 16);
}
__device__ __forceinline__ uint32_t split_pair_hi(float a, float b, uint32_t& lo_out) {
    uint16_t ha, la, hb, lb;
    split_bf16(a, ha, la);
    split_bf16(b, hb, lb);
    lo_out = pack2(la, lb);
    return pack2(ha, hb);
}

// ---------------- fused prep: count_deg + split_x + split_w1 + split_w2 ----------------
#define CD_BLOCKS 3321     // ceil(850000 / 256)
#define SX_ITEMS (N_NODES * IN_F / 4)          // 6.4M float4
#define SX_BLOCKS ((SX_ITEMS + 255) / 256)     // 25000
#define SW1_ITEMS ((IN_F / 2) * HID_F)         // 65536
#define SW1_BLOCKS (SW1_ITEMS / 256)           // 256
#define SW2_ITEMS ((HID_F / 2) * OUT_F)        // 16384
#define SW2_BLOCKS (SW2_ITEMS / 256)           // 64
#define PREP_BLOCKS (CD_BLOCKS + SX_BLOCKS + SW1_BLOCKS + SW2_BLOCKS)

__global__ void prep_kernel(const float* __restrict__ x,
                            const float* __restrict__ W1,
                            const float* __restrict__ W2,
                            const int* __restrict__ edst) {
    int b = blockIdx.x;
    int tid = threadIdx.x;
    if (b < CD_BLOCKS) {
        int e = b * 256 + tid;
        if (e < N_EDGES) atomicAdd(&g_deg[edst[e]], 1);
        return;
    }
    b -= CD_BLOCKS;
    if (b < SX_BLOCKS) {
        int i = b * 256 + tid;               // float4 index
        if (i >= SX_ITEMS) return;
        float4 v = reinterpret_cast<const float4*>(x)[i];
        uint2 hi, lo;
        hi.x = split_pair_hi(v.x, v.y, lo.x);
        hi.y = split_pair_hi(v.z, v.w, lo.y);
        reinterpret_cast<uint2*>(g_xhi)[i] = hi;
        reinterpret_cast<uint2*>(g_xlo)[i] = lo;
        return;
    }
    b -= SX_BLOCKS;
    if (b < SW1_BLOCKS) {
        int idx = b * 256 + tid;             // u32 index into W1 packed
        int k2 = idx >> 8;                   // / HID_F
        int n = idx & (HID_F - 1);
        float a = W1[(size_t)(2 * k2) * HID_F + n];
        float c = W1[(size_t)(2 * k2 + 1) * HID_F + n];
        uint32_t lo;
        g_w1hi[idx] = split_pair_hi(a, c, lo);
        g_w1lo[idx] = lo;
        return;
    }
    b -= SW1_BLOCKS;
    {
        int idx = b * 256 + tid;
        int k2 = idx >> 7;                   // / OUT_F
        int n = idx & (OUT_F - 1);
        float a = W2[(size_t)(2 * k2) * OUT_F + n];
        float c = W2[(size_t)(2 * k2 + 1) * OUT_F + n];
        uint32_t lo;
        g_w2hi[idx] = split_pair_hi(a, c, lo);
        g_w2lo[idx] = lo;
    }
}

// single block, 1024 threads: exclusive scan of degrees -> rowptr, plus inv_deg
__global__ void scan_kernel() {
    __shared__ int partial[1024];
    const int tid = threadIdx.x;
    const int CH = (N_NODES + 1023) / 1024;
    int start = tid * CH;
    int stop = start + CH;
    if (stop > N_NODES) stop = N_NODES;

    int s = 0;
    for (int i = start; i < stop; ++i) s += g_deg[i];
    partial[tid] = s;
    __syncthreads();
    for (int off = 1; off < 1024; off <<= 1) {
        int v = 0;
        if (tid >= off) v = partial[tid - off];
        __syncthreads();
        partial[tid] += v;
        __syncthreads();
    }
    int base = partial[tid] - s;
    for (int i = start; i < stop; ++i) {
        int d = g_deg[i];
        g_rowptr[i] = base;
        base += d;
        g_invdeg[i] = 1.0f / (float)(d > 0 ? d : 1);
    }
    if (tid == 0) g_rowptr[N_NODES] = partial[1023];
}

// ---------------- bf16 3-term MMA GEMM + fused build_csr blocks ----------------
__device__ __forceinline__ void mma_bf16(float* c, const uint32_t* a, const uint32_t* b) {
    asm volatile(
        "mma.sync.aligned.m16n8k16.row.col.f32.bf16.bf16.f32 "
        "{%0,%1,%2,%3}, {%4,%5,%6,%7}, {%8,%9}, {%0,%1,%2,%3};\n"
        : "+f"(c[0]), "+f"(c[1]), "+f"(c[2]), "+f"(c[3])
        : "r"(a[0]), "r"(a[1]), "r"(a[2]), "r"(a[3]), "r"(b[0]), "r"(b[1]));
}

__device__ __forceinline__ void cp_async16(void* smem_dst, const void* gmem_src, int src_bytes) {
    uint32_t s = (uint32_t)__cvta_generic_to_shared(smem_dst);
    asm volatile("cp.async.cg.shared.global [%0], [%1], 16, %2;\n"
                 :: "r"(s), "l"(gmem_src), "r"(src_bytes));
}
__device__ __forceinline__ void cp_commit() { asm volatile("cp.async.commit_group;\n"); }
template <int N>
__device__ __forceinline__ void cp_wait() { asm volatile("cp.async.wait_group %0;\n" :: "n"(N)); }

#define BM 128
#define BN 128
#define BKP 16
#define SA 20
#define SB 136
#define A_TILE (BM * SA)
#define B_TILE (BKP * SB)
#define SMEM_U32 (4 * A_TILE + 4 * B_TILE)   // 75776 B
#define GEMM_ROWS ((N_NODES + BM - 1) / BM)  // 391

// blocks with blockIdx.y >= gemm_rows run build_csr instead (one edge/thread).
__global__ __launch_bounds__(256, 2)
void gemm_bf16x2_kernel(const uint32_t* __restrict__ Ah, const uint32_t* __restrict__ Al,
                        const uint32_t* __restrict__ Bh, const uint32_t* __restrict__ Bl,
                        uint32_t* __restrict__ Ch, int M, int K2, int N,
                        const int* __restrict__ esrc, const int* __restrict__ edst,
                        const float* __restrict__ ew, int gemm_rows) {
    extern __shared__ uint32_t smem[];
    const int tid = threadIdx.x;

    if ((int)blockIdx.y >= gemm_rows) {
        // ---- build_csr part ----
        int lin = ((int)blockIdx.y - gemm_rows) * (int)gridDim.x + (int)blockIdx.x;
        int e = lin * 256 + tid;
        if (e < N_EDGES) {
            int dst = edst[e];
            int p = g_rowptr[dst] + atomicAdd(&g_pos[dst], 1);
            g_esrc[p] = esrc[e];
            g_ew[p] = ew[e];
        }
        return;
    }

    uint32_t* Abase = smem;
    uint32_t* Bbase = smem + 4 * A_TILE;

    const int wid = tid >> 5;
    const int lane = tid & 31;
    const int gid = lane >> 2;
    const int tig = lane & 3;
    const int warp_m = wid >> 1;
    const int warp_n = wid & 1;
    const int m_base = warp_m * 32;
    const int n_base = warp_n * 64;
    const int blockRow = blockIdx.y * BM;
    const int blockCol = blockIdx.x * BN;
    const int ntiles = K2 / BKP;

    float acc[2][8][4];
#pragma unroll
    for (int mt = 0; mt < 2; mt++)
#pragma unroll
        for (int nt = 0; nt < 8; nt++)
#pragma unroll
            for (int i = 0; i < 4; i++) acc[mt][nt][i] = 0.0f;

    auto load_tiles = [&](int t, int buf) {
        const int k0p = t * BKP;
        const uint32_t* Ag[2] = {Ah, Al};
        const uint32_t* Bg[2] = {Bh, Bl};
#pragma unroll
        for (int hl = 0; hl < 2; hl++) {
            uint32_t* Asb = Abase + (buf * 2 + hl) * A_TILE;
#pragma unroll
            for (int i = 0; i < 2; i++) {
                int idx = tid + i * 256;
                int row = idx >> 2;
                int c4 = idx & 3;
                int gr = blockRow + row;
                int inb = (gr < M);
                int grc = inb ? gr : 0;
                cp_async16(&Asb[row * SA + c4 * 4],
                           Ag[hl] + (size_t)grc * K2 + k0p + c4 * 4, inb ? 16 : 0);
            }
            uint32_t* Bsb = Bbase + (buf * 2 + hl) * B_TILE;
#pragma unroll
            for (int i = 0; i < 2; i++) {
                int idx = tid + i * 256;
                int row = idx >> 5;
                int c4 = idx & 31;
                cp_async16(&Bsb[row * SB + c4 * 4],
                           Bg[hl] + (size_t)(k0p + row) * N + blockCol + c4 * 4, 16);
            }
        }
    };

    load_tiles(0, 0);
    cp_commit();

    for (int t = 0; t < ntiles; ++t) {
        const int buf = t & 1;
        if (t + 1 < ntiles) {
            load_tiles(t + 1, (t + 1) & 1);
            cp_commit();
            cp_wait<1>();
        } else {
            cp_wait<0>();
        }
        __syncthreads();

        const uint32_t* Ah_s = Abase + (buf * 2 + 0) * A_TILE;
        const uint32_t* Al_s = Abase + (buf * 2 + 1) * A_TILE;
        const uint32_t* Bh_s = Bbase + (buf * 2 + 0) * B_TILE;
        const uint32_t* Bl_s = Bbase + (buf * 2 + 1) * B_TILE;

#pragma unroll
        for (int kk = 0; kk < 2; kk++) {
            const int jb = kk * 8;
            uint32_t ah[2][4], al[2][4];
#pragma unroll
            for (int mt = 0; mt < 2; mt++) {
                int r0 = m_base + mt * 16 + gid;
                int o0 = r0 * SA + jb + tig;
                int o1 = (r0 + 8) * SA + jb + tig;
                ah[mt][0] = Ah_s[o0];
                ah[mt][1] = Ah_s[o1];
                ah[mt][2] = Ah_s[o0 + 4];
                ah[mt][3] = Ah_s[o1 + 4];
                al[mt][0] = Al_s[o0];
                al[mt][1] = Al_s[o1];
                al[mt][2] = Al_s[o0 + 4];
                al[mt][3] = Al_s[o1 + 4];
            }
            uint32_t bh[8][2], bl[8][2];
#pragma unroll
            for (int nt = 0; nt < 8; nt++) {
                int col = n_base + nt * 8 + gid;
                int o0 = (jb + tig) * SB + col;
                int o1 = (jb + tig + 4) * SB + col;
                bh[nt][0] = Bh_s[o0];
                bh[nt][1] = Bh_s[o1];
                bl[nt][0] = Bl_s[o0];
                bl[nt][1] = Bl_s[o1];
            }
#pragma unroll
            for (int mt = 0; mt < 2; mt++) {
#pragma unroll
                for (int nt = 0; nt < 8; nt++) {
                    mma_bf16(acc[mt][nt], ah[mt], bh[nt]);
                    mma_bf16(acc[mt][nt], ah[mt], bl[nt]);
                    mma_bf16(acc[mt][nt], al[mt], bh[nt]);
                }
            }
        }
        __syncthreads();
    }

#pragma unroll
    for (int mt = 0; mt < 2; mt++) {
#pragma unroll
        for (int nt = 0; nt < 8; nt++) {
            int r = blockRow + m_base + mt * 16 + gid;
            int c = blockCol + n_base + nt * 8 + tig * 2;
            if (r < M) {
                __half2 p = __floats2half2_rn(acc[mt][nt][0], acc[mt][nt][1]);
                Ch[((size_t)r * N + c) >> 1] = *reinterpret_cast<uint32_t*>(&p);
            }
            if (r + 8 < M) {
                __half2 p = __floats2half2_rn(acc[mt][nt][2], acc[mt][nt][3]);
                Ch[((size_t)(r + 8) * N + c) >> 1] = *reinterpret_cast<uint32_t*>(&p);
            }
        }
    }
}

// ---------------- gather-side aggregation (fp16 features, f32 accum) ----------------
__device__ __forceinline__ void acc_fma8(float* a, uint4 v, float w) {
    float2 p;
    p = __half22float2(*reinterpret_cast<__half2*>(&v.x)); a[0] += w * p.x; a[1] += w * p.y;
    p = __half22float2(*reinterpret_cast<__half2*>(&v.y)); a[2] += w * p.x; a[3] += w * p.y;
    p = __half22float2(*reinterpret_cast<__half2*>(&v.z)); a[4] += w * p.x; a[5] += w * p.y;
    p = __half22float2(*reinterpret_cast<__half2*>(&v.w)); a[6] += w * p.x; a[7] += w * p.y;
}

// Layer 1: 256 fp16 feats/node = one uint4 per lane. One warp per node.
__global__ void aggregate1_kernel(const float* __restrict__ bias) {
    int gw = (blockIdx.x * blockDim.x + threadIdx.x) >> 5;
    int lane = threadIdx.x & 31;
    if (gw >= N_NODES) return;
    int beg = g_rowptr[gw], end = g_rowptr[gw + 1];

    float a[8];
#pragma unroll
    for (int i = 0; i < 8; i++) a[i] = 0.0f;

    const uint4* feat = reinterpret_cast<const uint4*>(g_hw1h);
    int e = beg;
    for (; e + 1 < end; e += 2) {
        int s0 = g_esrc[e];
        int s1 = g_esrc[e + 1];
        float w0 = g_ew[e];
        float w1 = g_ew[e + 1];
        uint4 v0 = __ldg(feat + (size_t)s0 * 32 + lane);
        uint4 v1 = __ldg(feat + (size_t)s1 * 32 + lane);
        acc_fma8(a, v0, w0);
        acc_fma8(a, v1, w1);
    }
    if (e < end) {
        int s0 = g_esrc[e];
        float w0 = g_ew[e];
        uint4 v0 = __ldg(feat + (size_t)s0 * 32 + lane);
        acc_fma8(a, v0, w0);
    }

    float inv = g_invdeg[gw];
    const float4* bp = reinterpret_cast<const float4*>(bias);
    float4 bA = bp[lane * 2];
    float4 bB = bp[lane * 2 + 1];
    float o[8];
    o[0] = fmaxf(a[0] * inv + bA.x, 0.f);
    o[1] = fmaxf(a[1] * inv + bA.y, 0.f);
    o[2] = fmaxf(a[2] * inv + bA.z, 0.f);
    o[3] = fmaxf(a[3] * inv + bA.w, 0.f);
    o[4] = fmaxf(a[4] * inv + bB.x, 0.f);
    o[5] = fmaxf(a[5] * inv + bB.y, 0.f);
    o[6] = fmaxf(a[6] * inv + bB.z, 0.f);
    o[7] = fmaxf(a[7] * inv + bB.w, 0.f);

    uint4 ph, pl;
    ph.x = split_pair_hi(o[0], o[1], pl.x);
    ph.y = split_pair_hi(o[2], o[3], pl.y);
    ph.z = split_pair_hi(o[4], o[5], pl.z);
    ph.w = split_pair_hi(o[6], o[7], pl.w);
    size_t oidx = (size_t)gw * 32 + lane;
    reinterpret_cast<uint4*>(g_hhi)[oidx] = ph;
    reinterpret_cast<uint4*>(g_hlo)[oidx] = pl;
}

// Layer 2: 128 fp16 feats/node = one uint2 per lane. One warp per node.
__global__ void aggregate2_kernel(const float* __restrict__ bias, float* __restrict__ out) {
    int gw = (blockIdx.x * blockDim.x + threadIdx.x) >> 5;
    int lane = threadIdx.x & 31;
    if (gw >= N_NODES) return;
    int beg = g_rowptr[gw], end = g_rowptr[gw + 1];

    float a[4];
#pragma unroll
    for (int i = 0; i < 4; i++) a[i] = 0.0f;

    const uint2* feat = reinterpret_cast<const uint2*>(g_hw2h);
    int e = beg;
    for (; e + 1 < end; e += 2) {
        int s0 = g_esrc[e];
        int s1 = g_esrc[e + 1];
        float w0 = g_ew[e];
        float w1 = g_ew[e + 1];
        uint2 v0 = __ldg(feat + (size_t)s0 * 32 + lane);
        uint2 v1 = __ldg(feat + (size_t)s1 * 32 + lane);
        float2 p;
        p = __half22float2(*reinterpret_cast<__half2*>(&v0.x)); a[0] += w0 * p.x; a[1] += w0 * p.y;
        p = __half22float2(*reinterpret_cast<__half2*>(&v0.y)); a[2] += w0 * p.x; a[3] += w0 * p.y;
        p = __half22float2(*reinterpret_cast<__half2*>(&v1.x)); a[0] += w1 * p.x; a[1] += w1 * p.y;
        p = __half22float2(*reinterpret_cast<__half2*>(&v1.y)); a[2] += w1 * p.x; a[3] += w1 * p.y;
    }
    if (e < end) {
        int s0 = g_esrc[e];
        float w0 = g_ew[e];
        uint2 v0 = __ldg(feat + (size_t)s0 * 32 + lane);
        float2 p;
        p = __half22float2(*reinterpret_cast<__half2*>(&v0.x)); a[0] += w0 * p.x; a[1] += w0 * p.y;
        p = __half22float2(*reinterpret_cast<__half2*>(&v0.y)); a[2] += w0 * p.x; a[3] += w0 * p.y;
    }

    float inv = g_invdeg[gw];
    float4 b0 = reinterpret_cast<const float4*>(bias)[lane];
    float4 o0;
    o0.x = a[0] * inv + b0.x;
    o0.y = a[1] * inv + b0.y;
    o0.z = a[2] * inv + b0.z;
    o0.w = a[3] * inv + b0.w;
    reinterpret_cast<float4*>(out)[(size_t)gw * 32 + lane] = o0;
}

// ---------------- launch ----------------
extern "C" void kernel_launch(void* const* d_in, const int* in_sizes, int n_in,
                              void* d_out, int out_size) {
    const float* x    = (const float*)d_in[0];
    const float* W1   = (const float*)d_in[1];
    const float* b1   = (const float*)d_in[2];
    const float* W2   = (const float*)d_in[3];
    const float* b2   = (const float*)d_in[4];
    const float* ew   = (const float*)d_in[5];
    const int*   esrc = (const int*)d_in[6];
    const int*   edst = (const int*)d_in[7];
    float* out = (float*)d_out;

    void *p_hw1h, *p_hw2h, *p_xhi, *p_xlo, *p_hhi, *p_hlo;
    void *p_w1hi, *p_w1lo, *p_w2hi, *p_w2lo, *p_deg, *p_pos;
    cudaGetSymbolAddress(&p_hw1h, g_hw1h);
    cudaGetSymbolAddress(&p_hw2h, g_hw2h);
    cudaGetSymbolAddress(&p_xhi, g_xhi);
    cudaGetSymbolAddress(&p_xlo, g_xlo);
    cudaGetSymbolAddress(&p_hhi, g_hhi);
    cudaGetSymbolAddress(&p_hlo, g_hlo);
    cudaGetSymbolAddress(&p_w1hi, g_w1hi);
    cudaGetSymbolAddress(&p_w1lo, g_w1lo);
    cudaGetSymbolAddress(&p_w2hi, g_w2hi);
    cudaGetSymbolAddress(&p_w2lo, g_w2lo);
    cudaGetSymbolAddress(&p_deg, g_deg);
    cudaGetSymbolAddress(&p_pos, g_pos);

    cudaFuncSetAttribute(gemm_bf16x2_kernel,
                         cudaFuncAttributeMaxDynamicSharedMemorySize, SMEM_U32 * 4);

    cudaMemsetAsync(p_deg, 0, N_NODES * sizeof(int));          // launch 1
    cudaMemsetAsync(p_pos, 0, N_NODES * sizeof(int));          // launch 2

    prep_kernel<<<PREP_BLOCKS, 256>>>(x, W1, W2, edst);        // launch 3
    scan_kernel<<<1, 1024>>>();                                // launch 4

    // hw1 = x @ W1 -> fp16, with build_csr fused as extra grid rows (launch 5)
    {
        const int CSR_ROWS = (N_EDGES + 2 * 256 - 1) / (2 * 256);  // 1661 (gridDim.x = 2)
        dim3 grid(HID_F / BN, GEMM_ROWS + CSR_ROWS);
        gemm_bf16x2_kernel<<<grid, 256, SMEM_U32 * 4>>>(
            (const uint32_t*)p_xhi, (const uint32_t*)p_xlo,
            (const uint32_t*)p_w1hi, (const uint32_t*)p_w1lo,
            (uint32_t*)p_hw1h, N_NODES, IN_F / 2, HID_F,
            esrc, edst, ew, GEMM_ROWS);
    }

    // h = relu(agg(hw1)*invdeg + b1), emitted pre-split      (launch 6 -> ncu)
    aggregate1_kernel<<<(N_NODES * 32 + 255) / 256, 256>>>(b1);

    // hw2 = h @ W2 -> fp16 (no csr rows)                      (launch 7)
    gemm_bf16x2_kernel<<<dim3(OUT_F / BN, GEMM_ROWS), 256, SMEM_U32 * 4>>>(
        (const uint32_t*)p_hhi, (const uint32_t*)p_hlo,
        (const uint32_t*)p_w2hi, (const uint32_t*)p_w2lo,
        (uint32_t*)p_hw2h, N_NODES, HID_F / 2, OUT_F,
        nullptr, nullptr, nullptr, GEMM_ROWS);

    // out = agg(hw2)*invdeg + b2                              (launch 8)
    aggregate2_kernel<<<(N_NODES * 32 + 255) / 256, 256>>>(b2, out);
}